// round 4
// baseline (speedup 1.0000x reference)
#include <cuda_runtime.h>
#include <cuda_bf16.h>
#include <stdint.h>

#define BUCKET_SIZE 512
#define WPB   4              // warps per pass1 block
#define GB1   296            // pass1 blocks -> W = 1184 warp-tiles
#define W     (GB1 * WPB)
#define RG    16             // row-groups for hierarchical scan
#define RPG   ((W + RG - 1) / RG)   // 74 rows per group
#define GB3   1184           // pass3 blocks
#define MAXNB 8192           // actual nb = 7813
#define MAXN  4194304        // actual n = 4,000,000

// [w][nb] per-warp-tile bucket counts (u16) and exclusive offsets (u32)
__device__ unsigned short g_hist[(size_t)W * MAXNB];   // 19.4 MB
__device__ unsigned       g_off [(size_t)W * MAXNB];   // 38.8 MB
__device__ unsigned       g_part[(size_t)RG * MAXNB];  // 512 KB
__device__ unsigned       g_word[MAXN];                // bucket<<12 | local_rank

// ---- Pass 1: warp-private stable local rank + per-warp histogram (NO barriers in loop) ----
__global__ __launch_bounds__(32 * WPB) void psh_pass1(
    const float* __restrict__ coords, const int* __restrict__ seps,
    const int* __restrict__ hop_p, int n, int nB, int nb, int wtile,
    unsigned long long magic_nb, float* __restrict__ out_bucket,
    unsigned* __restrict__ words)
{
    extern __shared__ unsigned short cnt[];     // [WPB][nb]
    const int lane = threadIdx.x & 31;
    const int wid  = threadIdx.x >> 5;
    unsigned short* cw = cnt + wid * nb;

    // zero all warp counters (WPB*nb is even -> u32 stores)
    const int nz32 = (WPB * nb) >> 1;
    for (int j = threadIdx.x; j < nz32; j += 32 * WPB)
        ((unsigned*)cnt)[j] = 0u;
    __syncthreads();

    const unsigned hop = (unsigned)hop_p[0];
    const int w   = blockIdx.x * WPB + wid;
    const int beg = w * wtile;
    const int end = min(n, beg + wtile);

    // bid(i) = #{k : seps[k] <= i}; only seps inside (beg, end-1] vary
    int klo = 0, khi = 0;
    if (beg < end) {
        for (int k = 0; k < nB; k++) {
            int s = __ldg(&seps[k]);
            klo += (s <= beg);
            khi += (s <= end - 1);
        }
    }

    for (int c = beg; c < end; c += 32) {
        int i = c + lane;
        bool v = (i < end);
        unsigned vm = __ballot_sync(0xffffffffu, v);
        unsigned b = 0, mask = 0;
        int leader = 0, intra = 0, g = 0;
        if (v) {
            float x = coords[3*i], y = coords[3*i+1], z = coords[3*i+2];
            unsigned bid = (unsigned)klo;
            for (int k = klo; k < khi; k++) bid += (__ldg(&seps[k]) <= i);
            unsigned vx = (unsigned)(int)floorf(x);
            unsigned vy = (unsigned)(int)floorf(y);
            unsigned vz = (unsigned)(int)floorf(z);
            unsigned h = vx * 73856093u ^ vy * 19349663u ^ vz * 83492791u
                       ^ bid * 2654435761u;
            h += hop;
            unsigned q = (unsigned)__umul64hi((unsigned long long)h, magic_nb);
            b = h - q * (unsigned)nb;
            mask   = __match_any_sync(vm, b);
            leader = __ffs(mask) - 1;
            intra  = __popc(mask & ((1u << lane) - 1u));
            g      = __popc(mask);
        }
        int base = 0;
        if (v && lane == leader) {               // warp-private RMW: no atomics
            base = (int)cw[b];
            cw[b] = (unsigned short)(base + g);
        }
        if (v) {
            base = __shfl_sync(mask, base, leader);
            unsigned lr = (unsigned)(base + intra);   // < 4096
            words[i] = (b << 12) | lr;
            out_bucket[i] = (float)b;
        }
    }

    // each warp flushes its own row (coalesced u16)
    unsigned short* gh = g_hist + (size_t)w * nb;
    for (int j = lane; j < nb; j += 32) gh[j] = cw[j];
}

// ---- Pass 2a: column-parallel partial sums over each row-group ----
__global__ __launch_bounds__(256) void psh_pass2a(int nb)
{
    int j = blockIdx.x * 256 + threadIdx.x;
    int rg = blockIdx.y;
    if (j >= nb) return;
    int r0 = rg * RPG, r1 = min(W, r0 + RPG);
    unsigned s = 0;
    #pragma unroll 8
    for (int r = r0; r < r1; r++) s += (unsigned)g_hist[(size_t)r * nb + j];
    g_part[(size_t)rg * nb + j] = s;
}

// ---- Pass 2b: scan the 16 partials per bucket; counts + deficit zero-fill ----
__global__ __launch_bounds__(256) void psh_pass2b(
    int nb, float* __restrict__ out_counts, float* __restrict__ out_coord)
{
    int j = blockIdx.x * 256 + threadIdx.x;
    if (j >= nb) return;
    unsigned carry = 0;
    #pragma unroll
    for (int rg = 0; rg < RG; rg++) {
        unsigned v = g_part[(size_t)rg * nb + j];
        g_part[(size_t)rg * nb + j] = carry;
        carry += v;
    }
    out_counts[j] = (float)carry;
    int filled = min((int)carry, BUCKET_SIZE);
    float* dst = out_coord + ((size_t)j * BUCKET_SIZE + filled) * 3;
    int nz = (BUCKET_SIZE - filled) * 3;
    #pragma unroll 4
    for (int t = 0; t < nz; t++) dst[t] = 0.0f;
}

// ---- Pass 2c: rescan rows within each group -> full exclusive offsets ----
__global__ __launch_bounds__(256) void psh_pass2c(int nb)
{
    int j = blockIdx.x * 256 + threadIdx.x;
    int rg = blockIdx.y;
    if (j >= nb) return;
    int r0 = rg * RPG, r1 = min(W, r0 + RPG);
    unsigned carry = g_part[(size_t)rg * nb + j];
    #pragma unroll 8
    for (int r = r0; r < r1; r++) {
        size_t idx = (size_t)r * nb + j;
        unsigned v = (unsigned)g_hist[idx];
        g_off[idx] = carry;
        carry += v;
    }
}

// ---- Pass 3: barrier-free streaming scatter ----
__global__ __launch_bounds__(256) void psh_pass3(
    const float* __restrict__ coords, const unsigned* __restrict__ words,
    int n, int nb, unsigned long long magic_w, float* __restrict__ out_coord)
{
    const int tile = (n + GB3 - 1) / GB3;
    const int beg = blockIdx.x * tile;
    const int end = min(n, beg + tile);
    for (int i = beg + threadIdx.x; i < end; i += 256) {
        unsigned wd = words[i];
        float x = coords[3*i], y = coords[3*i+1], z = coords[3*i+2];
        unsigned b  = wd >> 12;
        unsigned lr = wd & 4095u;
        unsigned wt = (unsigned)__umul64hi((unsigned long long)i, magic_w);
        unsigned rank = __ldg(&g_off[(size_t)wt * nb + b]) + lr;
        if (rank < BUCKET_SIZE) {
            size_t s = ((size_t)b * BUCKET_SIZE + rank) * 3;
            out_coord[s + 0] = x;
            out_coord[s + 1] = y;
            out_coord[s + 2] = z;
        }
    }
}

extern "C" void kernel_launch(void* const* d_in, const int* in_sizes, int n_in,
                              void* d_out, int out_size)
{
    const float* coords = (const float*)d_in[0];
    const int*   seps   = (const int*)d_in[1];
    const int*   hop_p  = (const int*)d_in[2];

    const int n  = in_sizes[0] / 3;
    const int nB = in_sizes[1];
    const int pad_to = ((n + BUCKET_SIZE - 1) / BUCKET_SIZE) * BUCKET_SIZE;
    const int nb = pad_to / BUCKET_SIZE;
    const int wtile = (n + W - 1) / W;   // 3379 for n=4M (< 4096: fits 12 bits)

    float* out_coord  = (float*)d_out;
    float* out_counts = out_coord + (size_t)pad_to * 3;
    float* out_bucket = out_counts + nb;

    unsigned long long magic_nb = (~0ULL) / (unsigned)nb + 1ULL;      // h % nb
    unsigned long long magic_w  = (~0ULL) / (unsigned)wtile + 1ULL;   // i / wtile

    unsigned* words = nullptr;
    cudaGetSymbolAddress((void**)&words, g_word);

    size_t sh1 = (size_t)WPB * nb * sizeof(unsigned short);  // 62.5 KB

    static bool attr_set = false;
    if (!attr_set) {
        cudaFuncSetAttribute(psh_pass1,
                             cudaFuncAttributeMaxDynamicSharedMemorySize,
                             WPB * MAXNB * (int)sizeof(unsigned short));
        attr_set = true;
    }

    dim3 g2((nb + 255) / 256, RG);
    psh_pass1<<<GB1, 32 * WPB, sh1>>>(coords, seps, hop_p, n, nB, nb, wtile,
                                      magic_nb, out_bucket, words);
    psh_pass2a<<<g2, 256>>>(nb);
    psh_pass2b<<<(nb + 255) / 256, 256>>>(nb, out_counts, out_coord);
    psh_pass2c<<<g2, 256>>>(nb);
    psh_pass3<<<GB3, 256>>>(coords, words, n, nb, magic_w, out_coord);
}